// round 2
// baseline (speedup 1.0000x reference)
#include <cuda_runtime.h>
#include <cuda_bf16.h>

// ---------------------------------------------------------------------------
// GCN layer: h = dropout(relu( segsum_dst( (feat*rsqrt(deg_out))[src] ) @ W
//                              * rsqrt(deg_in) + b ))
// Shapes: feat [50000,256], W [256,256], b[256], src/dst [400000], out [50000,256]
// ---------------------------------------------------------------------------

#define N_NODES   50000
#define D_FEAT    256
#define N_TOTAL   (N_NODES * D_FEAT)          // 12,800,000
#define N_WORDS   (N_TOTAL / 32)              // 400,000 mask words

// Scratch (static device globals; no allocation allowed)
__device__ float        g_agg[N_TOTAL];       // 51.2 MB aggregation buffer (D_in space)
__device__ float        g_rs_out[N_NODES];
__device__ float        g_rs_in[N_NODES];
__device__ int          g_deg_out[N_NODES];
__device__ int          g_deg_in[N_NODES];
__device__ unsigned int g_mask[N_WORDS];      // 12.8M dropout bits

// ---------------------------------------------------------------------------
// threefry2x32 (JAX PRNG), key = (0, 42)
// ---------------------------------------------------------------------------
__device__ __forceinline__ unsigned int rotl32(unsigned int x, int r) {
    return (x << r) | (x >> (32 - r));
}

__device__ __forceinline__ void threefry2x32(unsigned int k0, unsigned int k1,
                                             unsigned int x0, unsigned int x1,
                                             unsigned int& o0, unsigned int& o1) {
    unsigned int ks2 = k0 ^ k1 ^ 0x1BD11BDAu;
    x0 += k0; x1 += k1;
#define TF_RND(r) { x0 += x1; x1 = rotl32(x1, r); x1 ^= x0; }
    TF_RND(13) TF_RND(15) TF_RND(26) TF_RND(6)
    x0 += k1;  x1 += ks2 + 1u;
    TF_RND(17) TF_RND(29) TF_RND(16) TF_RND(24)
    x0 += ks2; x1 += k0 + 2u;
    TF_RND(13) TF_RND(15) TF_RND(26) TF_RND(6)
    x0 += k0;  x1 += k1 + 3u;
    TF_RND(17) TF_RND(29) TF_RND(16) TF_RND(24)
    x0 += k1;  x1 += ks2 + 4u;
    TF_RND(13) TF_RND(15) TF_RND(26) TF_RND(6)
    x0 += ks2; x1 += k0 + 5u;
#undef TF_RND
    o0 = x0; o1 = x1;
}

__device__ __forceinline__ bool keep_from_bits(unsigned int bits) {
    // JAX uniform: f = bitcast((bits>>9)|0x3f800000) - 1.0;  keep = f < 0.9f
    float f = __uint_as_float((bits >> 9) | 0x3f800000u) - 1.0f;
    return f < 0.9f;
}

// ---------------------------------------------------------------------------
// Kernel 1: zero scratch
// ---------------------------------------------------------------------------
__global__ void k_zero() {
    int i = blockIdx.x * blockDim.x + threadIdx.x;   // N_TOTAL/4 threads
    if (i < N_TOTAL / 4) {
        ((float4*)g_agg)[i] = make_float4(0.f, 0.f, 0.f, 0.f);
    }
    if (i < N_NODES) {
        g_deg_out[i] = 0;
        g_deg_in[i]  = 0;
    }
}

// ---------------------------------------------------------------------------
// Kernel 2: degrees
// ---------------------------------------------------------------------------
__global__ void k_degrees(const int* __restrict__ src, const int* __restrict__ dst, int nE) {
    int e = blockIdx.x * blockDim.x + threadIdx.x;
    if (e < nE) {
        atomicAdd(&g_deg_out[src[e]], 1);
        atomicAdd(&g_deg_in[dst[e]], 1);
    }
}

// ---------------------------------------------------------------------------
// Kernel 3: rsqrt of clamped degrees
// ---------------------------------------------------------------------------
__global__ void k_rsqrt(int nN) {
    int i = blockIdx.x * blockDim.x + threadIdx.x;
    if (i < nN) {
        int dout = g_deg_out[i]; if (dout < 1) dout = 1;
        int din  = g_deg_in[i];  if (din  < 1) din  = 1;
        g_rs_out[i] = rsqrtf((float)dout);
        g_rs_in[i]  = rsqrtf((float)din);
    }
}

// ---------------------------------------------------------------------------
// Kernel 4: edge scatter-aggregate (one warp per edge, vector reductions)
// ---------------------------------------------------------------------------
__global__ void k_scatter(const float* __restrict__ feat,
                          const int* __restrict__ src,
                          const int* __restrict__ dst, int nE) {
    int warp = (blockIdx.x * blockDim.x + threadIdx.x) >> 5;
    int lane = threadIdx.x & 31;
    if (warp >= nE) return;
    int s = src[warp];
    int d = dst[warp];
    float rs = g_rs_out[s];
    const float4* fr = (const float4*)(feat + (size_t)s * D_FEAT);
    float4* ar = (float4*)(g_agg + (size_t)d * D_FEAT);
#pragma unroll
    for (int u = 0; u < 2; u++) {
        int idx = lane + u * 32;             // 64 float4 per row
        float4 v = fr[idx];
        v.x *= rs; v.y *= rs; v.z *= rs; v.w *= rs;
        asm volatile("red.global.add.v4.f32 [%0], {%1,%2,%3,%4};"
                     :: "l"(ar + idx), "f"(v.x), "f"(v.y), "f"(v.z), "f"(v.w)
                     : "memory");
    }
}

// ---------------------------------------------------------------------------
// Kernel 5: dropout bitmask — JAX threefry_partitionable scheme.
// Per flat element idx: counter = 64-bit iota -> words (idx>>32, idx&0xffffffff)
// = (0, idx) here; bits = o0 ^ o1 (32-bit combiner); keep = u(bits) < 0.9.
// One thread packs 32 consecutive elements into one mask word.
// ---------------------------------------------------------------------------
__global__ void k_mask() {
    int t = blockIdx.x * blockDim.x + threadIdx.x;
    if (t >= N_WORDS) return;
    unsigned int base = (unsigned int)t * 32u;
    unsigned int w = 0u;
#pragma unroll 4
    for (int i = 0; i < 32; i++) {
        unsigned int o0, o1;
        threefry2x32(0u, 42u, 0u, base + i, o0, o1);
        w |= (unsigned int)keep_from_bits(o0 ^ o1) << i;
    }
    g_mask[t] = w;
}

// ---------------------------------------------------------------------------
// Kernel 6: GEMM (agg @ W) + fused epilogue (rs_in, bias, relu, dropout)
// 128x128 tile, BK=16, 256 threads, 8x8 per thread, packed f32x2 FMA.
// ---------------------------------------------------------------------------
#define BM 128
#define BN 128
#define BK 16
#define TM 8
#define TN 8

__device__ __forceinline__ unsigned long long pack2(float x, float y) {
    unsigned long long r;
    asm("mov.b64 %0, {%1, %2};" : "=l"(r) : "f"(x), "f"(y));
    return r;
}

__device__ __forceinline__ void ffma2(unsigned long long& d,
                                      unsigned long long a, unsigned long long b) {
    asm("fma.rn.f32x2 %0, %1, %2, %0;" : "+l"(d) : "l"(a), "l"(b));
}

__global__ __launch_bounds__(256, 2)
void k_gemm_epilogue(const float* __restrict__ Wm,
                     const float* __restrict__ bvec,
                     float* __restrict__ out, int M) {
    __shared__ float As[BK][BM + 4];
    __shared__ float Ws[BK][BN];

    int tid = threadIdx.x;
    int tx = tid & 15;          // 0..15 -> column group (8 cols each)
    int ty = tid >> 4;          // 0..15 -> row group (8 rows each)
    int bm = blockIdx.x * BM;
    int bn = blockIdx.y * BN;

    unsigned long long acc[TM][TN / 2];
#pragma unroll
    for (int i = 0; i < TM; i++)
#pragma unroll
        for (int p = 0; p < TN / 2; p++) acc[i][p] = 0ull;

    const float* A = g_agg;

    for (int k0 = 0; k0 < D_FEAT; k0 += BK) {
        // Load A tile (128 rows x 16 k), store transposed into As[k][row]
#pragma unroll
        for (int u = 0; u < 2; u++) {
            int f = tid + u * 256;            // 512 float4 total
            int r = f >> 2;                   // 0..127
            int c = (f & 3) << 2;             // 0,4,8,12
            int grow = bm + r;
            float4 v;
            if (grow < M)
                v = *(const float4*)(A + (size_t)grow * D_FEAT + k0 + c);
            else
                v = make_float4(0.f, 0.f, 0.f, 0.f);
            As[c + 0][r] = v.x;
            As[c + 1][r] = v.y;
            As[c + 2][r] = v.z;
            As[c + 3][r] = v.w;
        }
        // Load W tile (16 k x 128 cols)
#pragma unroll
        for (int u = 0; u < 2; u++) {
            int f = tid + u * 256;
            int r = f >> 5;                   // 0..15
            int c = (f & 31) << 2;            // 0..124
            *(float4*)&Ws[r][c] = *(const float4*)(Wm + (size_t)(k0 + r) * D_FEAT + bn + c);
        }
        __syncthreads();

#pragma unroll
        for (int k = 0; k < BK; k++) {
            unsigned long long ap[TM];
#pragma unroll
            for (int i = 0; i < TM; i++) {
                float a = As[k][ty * TM + i];
                ap[i] = pack2(a, a);
            }
            union { float4 f4[2]; unsigned long long u[4]; } wv;
            wv.f4[0] = *(float4*)&Ws[k][tx * TN];
            wv.f4[1] = *(float4*)&Ws[k][tx * TN + 4];
#pragma unroll
            for (int i = 0; i < TM; i++)
#pragma unroll
                for (int p = 0; p < TN / 2; p++)
                    ffma2(acc[i][p], ap[i], wv.u[p]);
        }
        __syncthreads();
    }

    // Epilogue: * rs_in + b, relu, dropout, store
    int colBase = bn + tx * TN;
    float bias[TN];
    {
        float4 b0 = *(const float4*)(bvec + colBase);
        float4 b1 = *(const float4*)(bvec + colBase + 4);
        bias[0] = b0.x; bias[1] = b0.y; bias[2] = b0.z; bias[3] = b0.w;
        bias[4] = b1.x; bias[5] = b1.y; bias[6] = b1.z; bias[7] = b1.w;
    }
    const float inv_keep = 1.0f / 0.9f;
#pragma unroll
    for (int i = 0; i < TM; i++) {
        int row = bm + ty * TM + i;
        if (row < M) {
            float rs = g_rs_in[row];
            union { unsigned long long u[4]; float f[8]; float4 q[2]; } r;
#pragma unroll
            for (int p = 0; p < TN / 2; p++) r.u[p] = acc[i][p];
            unsigned int flat0 = (unsigned int)row * D_FEAT + colBase;
            unsigned int mword = g_mask[flat0 >> 5];
            int sh = flat0 & 31;
#pragma unroll
            for (int j = 0; j < TN; j++) {
                float v = r.f[j] * rs + bias[j];
                v = fmaxf(v, 0.0f);
                v = ((mword >> (sh + j)) & 1u) ? v * inv_keep : 0.0f;
                r.f[j] = v;
            }
            *(float4*)(out + flat0)     = r.q[0];
            *(float4*)(out + flat0 + 4) = r.q[1];
        }
    }
}

// ---------------------------------------------------------------------------
// Launch
// ---------------------------------------------------------------------------
extern "C" void kernel_launch(void* const* d_in, const int* in_sizes, int n_in,
                              void* d_out, int out_size) {
    const float* feat = (const float*)d_in[0];
    const float* Wm   = (const float*)d_in[1];
    const float* bvec = (const float*)d_in[2];
    const int*   src  = (const int*)d_in[3];
    const int*   dst  = (const int*)d_in[4];
    float* out = (float*)d_out;

    int M  = in_sizes[0] / D_FEAT;   // 50000
    int nE = in_sizes[3];            // 400000

    int zthreads = N_TOTAL / 4;      // float4 zeroing
    k_zero<<<(zthreads + 255) / 256, 256>>>();
    k_degrees<<<(nE + 255) / 256, 256>>>(src, dst, nE);
    k_rsqrt<<<(M + 255) / 256, 256>>>(M);
    k_mask<<<(N_WORDS + 127) / 128, 128>>>();
    k_scatter<<<(nE + 7) / 8, 256>>>(feat, src, dst, nE);

    dim3 grid((M + BM - 1) / BM, D_FEAT / BN);
    k_gemm_epilogue<<<grid, 256>>>(Wm, bvec, out, M);
}